// round 13
// baseline (speedup 1.0000x reference)
#include <cuda_runtime.h>
#include <cstdint>

#define DENSE_L   1024
#define NUM_G     16
#define WIN       128                  // +-40 Gaussian reach around each 4-k group
#define JB        (WIN / 8)            // 16 j-blocks of 8 l each
#define RB        16                   // rows per buffer
#define XS_STRIDE 1032                 // smem row stride (floats); phase-conflict-free
#define NTHREADS  512
#define WG_ELEMS  (NUM_G * JB * 32)    // 8192 floats = 32KB; one 128B block per (g,jb)

// W layout: [g][jb] -> 128B block = [sub][jp2][kk][par]
__device__ float g_Wt[WG_ELEMS];

__device__ __forceinline__ int group_base(float w0, float w3) {
    float c = 0.5f * (w0 + w3);
    int bi = ((int)floorf(c) - 64) & ~3;
    bi = bi < 0 ? 0 : bi;
    bi = bi > (DENSE_L - WIN) ? (DENSE_L - WIN) : bi;
    return bi;
}

__global__ void precompute_kernel(const float* __restrict__ weight) {
    int idx = blockIdx.x * blockDim.x + threadIdx.x;
    if (idx >= WG_ELEMS) return;
    int par = idx & 1;
    int kk  = (idx >> 1) & 3;
    int jp2 = (idx >> 3) & 1;
    int sub = (idx >> 4) & 1;
    int jb  = (idx >> 5) & (JB - 1);
    int g   = idx >> 9;
    int base = group_base(weight[g * 4], weight[g * 4 + 3]);
    int l = base + jb * 8 + sub * 4 + jp2 * 2 + par;
    float d = (float)(l + 1) - weight[g * 4 + kk];
    g_Wt[idx] = expf(-d * d * 0.01f);
}

__device__ __forceinline__ void fma2(unsigned long long &a,
                                     unsigned long long xp,
                                     unsigned long long wp) {
    asm("fma.rn.f32x2 %0, %1, %2, %0;" : "+l"(a) : "l"(xp), "l"(wp));
}

__device__ __forceinline__ void cp16(void* dst_smem, const void* src_gmem) {
    unsigned int d = (unsigned int)__cvta_generic_to_shared(dst_smem);
    asm volatile("cp.async.cg.shared.global [%0], [%1], 16;\n" :: "r"(d), "l"(src_gmem));
}
__device__ __forceinline__ void cp_commit() { asm volatile("cp.async.commit_group;\n"); }
__device__ __forceinline__ void cp_wait1()  { asm volatile("cp.async.wait_group 1;\n" ::: "memory"); }
__device__ __forceinline__ void cp_wait0()  { asm volatile("cp.async.wait_group 0;\n" ::: "memory"); }

__device__ __forceinline__ void stage_tile(float* xb, const float* __restrict__ xg, int tid) {
    #pragma unroll
    for (int i = 0; i < (RB * DENSE_L / 4) / NTHREADS; i++) {
        int idx = tid + i * NTHREADS;
        int r   = idx >> 8;
        int c4  = idx & 255;
        cp16(&xb[r * XS_STRIDE + (c4 << 2)], &xg[(size_t)idx << 2]);
    }
}

extern __shared__ float smem_dyn[];

__global__ __launch_bounds__(NTHREADS, 1)
void sampling_kernel(const float* __restrict__ x,
                     const float* __restrict__ weight,
                     float* __restrict__ out,
                     int ntiles) {
    float* sbase = (float*)(((uintptr_t)smem_dyn + 127) & ~(uintptr_t)127);
    float* xs0 = sbase;
    float* xs1 = sbase + RB * XS_STRIDE;
    float* wgs = sbase + 2 * RB * XS_STRIDE;   // 132096B offset -> stays 128B aligned
    int tid = threadIdx.x;

    #pragma unroll
    for (int i = tid; i < WG_ELEMS; i += NTHREADS) wgs[i] = g_Wt[i];

    int g    = tid >> 5;
    int lane = tid & 31;
    int row  = lane >> 1;
    int sub  = lane & 1;
    int base = group_base(weight[g * 4], weight[g * 4 + 3]);

    const int G = gridDim.x;
    int t = blockIdx.x;

    if (t < ntiles) stage_tile(xs0, x + (long long)t * RB * DENSE_L, tid);
    cp_commit();

    int cur = 0;
    for (; t < ntiles; t += G) {
        int tn = t + G;
        if (tn < ntiles) {
            stage_tile(cur ? xs0 : xs1, x + (long long)tn * RB * DENSE_L, tid);
            cp_commit();
            cp_wait1();
        } else {
            cp_wait0();
        }
        __syncthreads();

        const float* xb   = cur ? xs1 : xs0;
        const float* xrow = xb + row * XS_STRIDE + base + sub * 4;
        const float* wp   = wgs + g * (JB * 32) + sub * 16;

        unsigned long long acc0 = 0ull, acc1 = 0ull, acc2 = 0ull, acc3 = 0ull;
        #pragma unroll
        for (int jb = 0; jb < JB; jb++) {
            ulonglong2 xv = *(const ulonglong2*)(xrow + jb * 8);
            const ulonglong2* wq = (const ulonglong2*)(wp + jb * 32);
            ulonglong2 wA = wq[0];   // jp2=0: k0 pair, k1 pair
            ulonglong2 wB = wq[1];   // jp2=0: k2 pair, k3 pair
            fma2(acc0, xv.x, wA.x);
            fma2(acc1, xv.x, wA.y);
            fma2(acc2, xv.x, wB.x);
            fma2(acc3, xv.x, wB.y);
            ulonglong2 wC = wq[2];   // jp2=1: k0, k1
            ulonglong2 wD = wq[3];   // jp2=1: k2, k3
            fma2(acc0, xv.y, wC.x);
            fma2(acc1, xv.y, wC.y);
            fma2(acc2, xv.y, wD.x);
            fma2(acc3, xv.y, wD.y);
        }

        unsigned long long o0 = __shfl_xor_sync(0xffffffffu, acc0, 1);
        unsigned long long o1 = __shfl_xor_sync(0xffffffffu, acc1, 1);
        unsigned long long o2 = __shfl_xor_sync(0xffffffffu, acc2, 1);
        unsigned long long o3 = __shfl_xor_sync(0xffffffffu, acc3, 1);
        float2 a0 = *(float2*)&acc0, b0 = *(float2*)&o0;
        float2 a1 = *(float2*)&acc1, b1 = *(float2*)&o1;
        float2 a2 = *(float2*)&acc2, b2 = *(float2*)&o2;
        float2 a3 = *(float2*)&acc3, b3 = *(float2*)&o3;
        if (sub == 0) {
            float4 res = make_float4(a0.x + a0.y + b0.x + b0.y,
                                     a1.x + a1.y + b1.x + b1.y,
                                     a2.x + a2.y + b2.x + b2.y,
                                     a3.x + a3.y + b3.x + b3.y);
            *(float4*)&out[((long long)t * RB + row) * 64 + g * 4] = res;
        }
        __syncthreads();
        cur ^= 1;
    }
}

extern "C" void kernel_launch(void* const* d_in, const int* in_sizes, int n_in,
                              void* d_out, int out_size) {
    const float* x      = (const float*)d_in[0];
    const float* weight = (const float*)d_in[1];
    float* out = (float*)d_out;
    int R = in_sizes[0] / DENSE_L;
    int ntiles = R / RB;

    size_t smem = (size_t)(2 * RB * XS_STRIDE + WG_ELEMS) * sizeof(float) + 128;
    cudaFuncSetAttribute((const void*)sampling_kernel,
                         cudaFuncAttributeMaxDynamicSharedMemorySize, (int)smem);

    int sms = 148;
    cudaDeviceGetAttribute(&sms, cudaDevAttrMultiProcessorCount, 0);

    precompute_kernel<<<(WG_ELEMS + 255) / 256, 256>>>(weight);
    sampling_kernel<<<sms, NTHREADS, smem>>>(x, weight, out, ntiles);
}

// round 14
// speedup vs baseline: 1.0705x; 1.0705x over previous
#include <cuda_runtime.h>
#include <cstdint>

#define DENSE_L   1024
#define NUM_G     16
#define WIN       160                  // +-48 reach, same as the 147.9us R6 config
#define JB        (WIN / 8)            // 20 j-blocks of 8 l
#define RB        16                   // rows per buffer
#define XS_STRIDE 1028                 // 2*1028 % 32 == 8 -> 2-row LDS.64 conflict-free
#define NTHREADS  512
#define WG_ELEMS  (NUM_G * JB * 32)    // 10240 floats = 40KB

// W layout: float index = g*640 + jb*32 + sub*8 + kk*2 + par
//   (per (g,jb): 128B block; per sub: 8 floats = [k0 pair][k1 pair][k2 pair][k3 pair])
__device__ float g_Wt[WG_ELEMS];

typedef unsigned long long ull;

__device__ __forceinline__ int group_base(float w0, float w3) {
    float c = 0.5f * (w0 + w3);
    int bi = ((int)floorf(c) - 80) & ~3;     // identical to R6 (147.9us) math
    bi = bi < 0 ? 0 : bi;
    bi = bi > (DENSE_L - WIN) ? (DENSE_L - WIN) : bi;
    return bi;
}

__global__ void precompute_kernel(const float* __restrict__ weight) {
    int idx = blockIdx.x * blockDim.x + threadIdx.x;
    if (idx >= WG_ELEMS) return;
    int par = idx & 1;
    int kk  = (idx >> 1) & 3;
    int sub = (idx >> 3) & 3;
    int jb  = (idx >> 5) % JB;
    int g   = idx / (JB * 32);
    int base = group_base(weight[g * 4], weight[g * 4 + 3]);
    int l = base + jb * 8 + sub * 2 + par;
    float d = (float)(l + 1) - weight[g * 4 + kk];
    g_Wt[idx] = expf(-d * d * 0.01f);
}

__device__ __forceinline__ void fma2(ull &a, ull xp, ull wp) {
    asm("fma.rn.f32x2 %0, %1, %2, %0;" : "+l"(a) : "l"(xp), "l"(wp));
}
__device__ __forceinline__ void add2(ull &a, ull b) {
    asm("add.rn.f32x2 %0, %0, %1;" : "+l"(a) : "l"(b));
}

__device__ __forceinline__ void cp16(void* dst_smem, const void* src_gmem) {
    unsigned int d = (unsigned int)__cvta_generic_to_shared(dst_smem);
    asm volatile("cp.async.cg.shared.global [%0], [%1], 16;\n" :: "r"(d), "l"(src_gmem));
}
__device__ __forceinline__ void cp_commit() { asm volatile("cp.async.commit_group;\n"); }
__device__ __forceinline__ void cp_wait1()  { asm volatile("cp.async.wait_group 1;\n" ::: "memory"); }
__device__ __forceinline__ void cp_wait0()  { asm volatile("cp.async.wait_group 0;\n" ::: "memory"); }

__device__ __forceinline__ void stage_tile(float* xb, const float* __restrict__ xg, int tid) {
    #pragma unroll
    for (int i = 0; i < (RB * DENSE_L / 4) / NTHREADS; i++) {
        int idx = tid + i * NTHREADS;
        int r   = idx >> 8;          // 256 float4 per row
        int c4  = idx & 255;
        cp16(&xb[r * XS_STRIDE + (c4 << 2)], &xg[(size_t)idx << 2]);
    }
}

extern __shared__ float smem_dyn[];

__global__ __launch_bounds__(NTHREADS, 1)
void sampling_kernel(const float* __restrict__ x,
                     const float* __restrict__ weight,
                     float* __restrict__ out,
                     int ntiles) {
    float* xs0 = smem_dyn;
    float* xs1 = smem_dyn + RB * XS_STRIDE;
    float* wgs = smem_dyn + 2 * RB * XS_STRIDE;
    int tid = threadIdx.x;

    #pragma unroll
    for (int i = tid; i < WG_ELEMS; i += NTHREADS) wgs[i] = g_Wt[i];

    int g    = tid >> 5;             // warp = k-group
    int lane = tid & 31;
    int slot = lane >> 2;            // 8 slots, 2 rows each
    int sub  = lane & 3;             // l-pair within each 8-l block
    int base = group_base(weight[g * 4], weight[g * 4 + 3]);

    const int G = gridDim.x;
    int t = blockIdx.x;

    if (t < ntiles) stage_tile(xs0, x + (long long)t * RB * DENSE_L, tid);
    cp_commit();

    int cur = 0;
    for (; t < ntiles; t += G) {
        int tn = t + G;
        if (tn < ntiles) {
            stage_tile(cur ? xs0 : xs1, x + (long long)tn * RB * DENSE_L, tid);
            cp_commit();
            cp_wait1();
        } else {
            cp_wait0();
        }
        __syncthreads();

        const float* xb    = cur ? xs1 : xs0;
        const float* xrow0 = xb + (2 * slot)     * XS_STRIDE + base + sub * 2;
        const float* xrow1 = xb + (2 * slot + 1) * XS_STRIDE + base + sub * 2;
        const float* wp    = wgs + g * (JB * 32) + sub * 8;

        // acc[r][k], packed (even-l, odd-l)
        ull a00 = 0, a01 = 0, a02 = 0, a03 = 0;
        ull a10 = 0, a11 = 0, a12 = 0, a13 = 0;

        #pragma unroll
        for (int jb = 0; jb < JB; jb++) {
            ull xa = *(const ull*)(xrow0 + jb * 8);            // row0: (x_l, x_l+1)
            ull xc = *(const ull*)(xrow1 + jb * 8);            // row1
            ulonglong2 w01 = *(const ulonglong2*)(wp + jb * 32);       // k0 pair, k1 pair
            ulonglong2 w23 = *(const ulonglong2*)(wp + jb * 32 + 4);   // k2 pair, k3 pair
            fma2(a00, xa, w01.x);
            fma2(a01, xa, w01.y);
            fma2(a02, xa, w23.x);
            fma2(a03, xa, w23.y);
            fma2(a10, xc, w01.x);
            fma2(a11, xc, w01.y);
            fma2(a12, xc, w23.x);
            fma2(a13, xc, w23.y);
        }

        // reduce across the 4 sub lanes of this slot
        add2(a00, __shfl_xor_sync(0xffffffffu, a00, 1));
        add2(a01, __shfl_xor_sync(0xffffffffu, a01, 1));
        add2(a02, __shfl_xor_sync(0xffffffffu, a02, 1));
        add2(a03, __shfl_xor_sync(0xffffffffu, a03, 1));
        add2(a10, __shfl_xor_sync(0xffffffffu, a10, 1));
        add2(a11, __shfl_xor_sync(0xffffffffu, a11, 1));
        add2(a12, __shfl_xor_sync(0xffffffffu, a12, 1));
        add2(a13, __shfl_xor_sync(0xffffffffu, a13, 1));
        add2(a00, __shfl_xor_sync(0xffffffffu, a00, 2));
        add2(a01, __shfl_xor_sync(0xffffffffu, a01, 2));
        add2(a02, __shfl_xor_sync(0xffffffffu, a02, 2));
        add2(a03, __shfl_xor_sync(0xffffffffu, a03, 2));
        add2(a10, __shfl_xor_sync(0xffffffffu, a10, 2));
        add2(a11, __shfl_xor_sync(0xffffffffu, a11, 2));
        add2(a12, __shfl_xor_sync(0xffffffffu, a12, 2));
        add2(a13, __shfl_xor_sync(0xffffffffu, a13, 2));

        if (sub == 0) {
            float2 f00 = *(float2*)&a00, f01 = *(float2*)&a01;
            float2 f02 = *(float2*)&a02, f03 = *(float2*)&a03;
            float2 f10 = *(float2*)&a10, f11 = *(float2*)&a11;
            float2 f12 = *(float2*)&a12, f13 = *(float2*)&a13;
            long long r0 = (long long)t * RB + 2 * slot;
            *(float4*)&out[r0 * 64 + g * 4] = make_float4(
                f00.x + f00.y, f01.x + f01.y, f02.x + f02.y, f03.x + f03.y);
            *(float4*)&out[(r0 + 1) * 64 + g * 4] = make_float4(
                f10.x + f10.y, f11.x + f11.y, f12.x + f12.y, f13.x + f13.y);
        }
        __syncthreads();
        cur ^= 1;
    }
}

extern "C" void kernel_launch(void* const* d_in, const int* in_sizes, int n_in,
                              void* d_out, int out_size) {
    const float* x      = (const float*)d_in[0];
    const float* weight = (const float*)d_in[1];
    float* out = (float*)d_out;
    int R = in_sizes[0] / DENSE_L;
    int ntiles = R / RB;                 // 8192

    size_t smem = (size_t)(2 * RB * XS_STRIDE + WG_ELEMS) * sizeof(float);  // 172544 B
    cudaFuncSetAttribute((const void*)sampling_kernel,
                         cudaFuncAttributeMaxDynamicSharedMemorySize, (int)smem);

    int sms = 148;
    cudaDeviceGetAttribute(&sms, cudaDevAttrMultiProcessorCount, 0);

    precompute_kernel<<<(WG_ELEMS + 255) / 256, 256>>>(weight);
    sampling_kernel<<<sms, NTHREADS, smem>>>(x, weight, out, ntiles);
}

// round 15
// speedup vs baseline: 1.5926x; 1.4877x over previous
#include <cuda_runtime.h>
#include <cstdint>

#define DENSE_L   1024
#define NUM_G     16
#define WIN       128                  // +-40 reach (validated R13: rel_err 1.9e-7)
#define JB        (WIN / 8)            // 16 j-blocks of 8 l
#define RB        16                   // rows per buffer
#define XS_STRIDE 1032                 // slot banks 8*slot -> conflict-free; float4-stageable
#define NTHREADS  512
#define WG_ELEMS  (NUM_G * JB * 32)    // 8192 floats

// W layout: idx = g*512 + jb*32 + sub*8 + kp*4 + kk2*2 + par
//   l = base + jb*8 + sub*2 + par ; k = g*4 + kp*2 + kk2
__device__ float g_Wt[WG_ELEMS];

typedef unsigned long long ull;

__device__ __forceinline__ int group_base(float w0, float w3) {
    float c = 0.5f * (w0 + w3);
    int bi = ((int)floorf(c) - 64) & ~3;
    bi = bi < 0 ? 0 : bi;
    bi = bi > (DENSE_L - WIN) ? (DENSE_L - WIN) : bi;
    return bi;
}

__global__ void precompute_kernel(const float* __restrict__ weight) {
    int idx = blockIdx.x * blockDim.x + threadIdx.x;
    if (idx >= WG_ELEMS) return;
    int par = idx & 1;
    int kk2 = (idx >> 1) & 1;
    int kp  = (idx >> 2) & 1;
    int sub = (idx >> 3) & 3;
    int jb  = (idx >> 5) & (JB - 1);
    int g   = idx >> 9;
    int base = group_base(weight[g * 4], weight[g * 4 + 3]);
    int l = base + jb * 8 + sub * 2 + par;
    int k = g * 4 + kp * 2 + kk2;
    float d = (float)(l + 1) - weight[k];
    g_Wt[idx] = expf(-d * d * 0.01f);
}

__device__ __forceinline__ void fma2(ull &a, ull xp, ull wp) {
    asm("fma.rn.f32x2 %0, %1, %2, %0;" : "+l"(a) : "l"(xp), "l"(wp));
}
__device__ __forceinline__ void add2(ull &a, ull b) {
    asm("add.rn.f32x2 %0, %0, %1;" : "+l"(a) : "l"(b));
}
__device__ __forceinline__ ull pack2(float lo, float hi) {
    ull u; asm("mov.b64 %0, {%1, %2};" : "=l"(u) : "f"(lo), "f"(hi)); return u;
}

__device__ __forceinline__ void cp16(void* dst_smem, const void* src_gmem) {
    unsigned int d = (unsigned int)__cvta_generic_to_shared(dst_smem);
    asm volatile("cp.async.cg.shared.global [%0], [%1], 16;\n" :: "r"(d), "l"(src_gmem));
}
__device__ __forceinline__ void cp_commit() { asm volatile("cp.async.commit_group;\n"); }
__device__ __forceinline__ void cp_wait1()  { asm volatile("cp.async.wait_group 1;\n" ::: "memory"); }
__device__ __forceinline__ void cp_wait0()  { asm volatile("cp.async.wait_group 0;\n" ::: "memory"); }

__device__ __forceinline__ void stage_tile(float* xb, const float* __restrict__ xg, int tid) {
    #pragma unroll
    for (int i = 0; i < (RB * DENSE_L / 4) / NTHREADS; i++) {
        int idx = tid + i * NTHREADS;
        int r   = idx >> 8;          // 256 float4 per row
        int c4  = idx & 255;
        cp16(&xb[r * XS_STRIDE + (c4 << 2)], &xg[(size_t)idx << 2]);
    }
}

extern __shared__ float smem_dyn[];

__global__ __launch_bounds__(NTHREADS, 1)
void sampling_kernel(const float* __restrict__ x,
                     const float* __restrict__ weight,
                     float* __restrict__ out,
                     int ntiles) {
    float* xs0 = smem_dyn;
    float* xs1 = smem_dyn + RB * XS_STRIDE;
    int tid = threadIdx.x;

    int g    = tid >> 5;             // warp = k-group (4 k)
    int lane = tid & 31;
    int slot = lane & 3;             // 4 slots; rows = slot + 4r
    int sub  = (lane >> 2) & 3;      // l-pair within 8-l block
    int kp   = (lane >> 4) & 1;      // k-pair within group
    int base = group_base(weight[g * 4], weight[g * 4 + 3]);

    // ---- Load this thread's W slice into registers ONCE (no W in tile loop) ----
    ull w0[JB], w1[JB];
    const float* wb = g_Wt + g * (JB * 32) + sub * 8 + kp * 4;
    #pragma unroll
    for (int jb = 0; jb < JB; jb++) {
        float4 v = *(const float4*)(wb + jb * 32);
        w0[jb] = pack2(v.x, v.y);    // k = 4g+2kp   : (par0, par1)
        w1[jb] = pack2(v.z, v.w);    // k = 4g+2kp+1
    }

    const int G = gridDim.x;
    int t = blockIdx.x;

    if (t < ntiles) stage_tile(xs0, x + (long long)t * RB * DENSE_L, tid);
    cp_commit();

    int cur = 0;
    for (; t < ntiles; t += G) {
        int tn = t + G;
        if (tn < ntiles) {
            stage_tile(cur ? xs0 : xs1, x + (long long)tn * RB * DENSE_L, tid);
            cp_commit();
            cp_wait1();
        } else {
            cp_wait0();
        }
        __syncthreads();

        const float* xb = cur ? xs1 : xs0;
        const float* xr = xb + slot * XS_STRIDE + base + sub * 2;

        ull aA[4] = {0, 0, 0, 0};    // rows slot+4r, k = 4g+2kp
        ull aB[4] = {0, 0, 0, 0};    // rows slot+4r, k = 4g+2kp+1
        #pragma unroll
        for (int jb = 0; jb < JB; jb++) {
            #pragma unroll
            for (int r = 0; r < 4; r++) {
                ull xa = *(const ull*)(xr + r * (4 * XS_STRIDE) + jb * 8);
                fma2(aA[r], xa, w0[jb]);
                fma2(aB[r], xa, w1[jb]);
            }
        }

        // reduce across the 4 sub lanes (lane bits 2-3)
        #pragma unroll
        for (int r = 0; r < 4; r++) {
            add2(aA[r], __shfl_xor_sync(0xffffffffu, aA[r], 4));
            add2(aB[r], __shfl_xor_sync(0xffffffffu, aB[r], 4));
            add2(aA[r], __shfl_xor_sync(0xffffffffu, aA[r], 8));
            add2(aB[r], __shfl_xor_sync(0xffffffffu, aB[r], 8));
        }

        if ((lane & 12) == 0) {      // sub == 0: lanes 0-3, 16-19
            #pragma unroll
            for (int r = 0; r < 4; r++) {
                float2 vA = *(float2*)&aA[r];
                float2 vB = *(float2*)&aB[r];
                long long row = (long long)t * RB + slot + 4 * r;
                *(float2*)&out[row * 64 + g * 4 + kp * 2] =
                    make_float2(vA.x + vA.y, vB.x + vB.y);
            }
        }
        __syncthreads();
        cur ^= 1;
    }
}

extern "C" void kernel_launch(void* const* d_in, const int* in_sizes, int n_in,
                              void* d_out, int out_size) {
    const float* x      = (const float*)d_in[0];
    const float* weight = (const float*)d_in[1];
    float* out = (float*)d_out;
    int R = in_sizes[0] / DENSE_L;
    int ntiles = R / RB;                 // 8192

    size_t smem = (size_t)(2 * RB * XS_STRIDE) * sizeof(float);  // 132096 B
    cudaFuncSetAttribute((const void*)sampling_kernel,
                         cudaFuncAttributeMaxDynamicSharedMemorySize, (int)smem);

    int sms = 148;
    cudaDeviceGetAttribute(&sms, cudaDevAttrMultiProcessorCount, 0);

    precompute_kernel<<<(WG_ELEMS + 255) / 256, 256>>>(weight);
    sampling_kernel<<<sms, NTHREADS, smem>>>(x, weight, out, ntiles);
}